// round 13
// baseline (speedup 1.0000x reference)
#include <cuda_runtime.h>

#define B_SZ   8192
#define IN_SZ  64
#define OUT_SZ 64
#define NS     8
#define NB     20
#define NI     19

#define ROWS_PER_BLK 4
#define NBLK   (B_SZ / ROWS_PER_BLK)     // 2048
#define PREP_BLOCKS 64                   // must be < 148 (wave-1 guarantee)
#define LN2f  0.69314718055994530942f
#define L2Ef  1.44269504088896340736f

// Precomputed per-(o,i) parameter tables, [i*OUT + o] layout (coalesced over o).
// PA = { b1*scale*ln2, b2*ln2, b3*log2e, b4 }
// PB = { b5..b8 * scale },  scale = softplus(raw_gamma)/OUT
__device__ float4 g_PA[IN_SZ * OUT_SZ];
__device__ float4 g_PB[IN_SZ * OUT_SZ];

// Device-side barrier state. Zero at first launch (static init); restored to
// zero at the end of EVERY launch by the last block to finish, so graph
// replays are deterministic.
__device__ unsigned g_done;       // prep o-columns published
__device__ unsigned g_consumed;   // blocks finished

__device__ __forceinline__ float ex2f(float x) {
    float y; asm("ex2.approx.ftz.f32 %0, %1;" : "=f"(y) : "f"(x)); return y;
}
__device__ __forceinline__ float lg2f(float x) {
    float y; asm("lg2.approx.ftz.f32 %0, %1;" : "=f"(y) : "f"(x)); return y;
}
__device__ __forceinline__ unsigned ld_acquire(const unsigned* p) {
    unsigned v;
    asm volatile("ld.global.acquire.gpu.u32 %0, [%1];" : "=r"(v) : "l"(p));
    return v;
}

// Compute table entry for (o, i): identical math to the old prep kernel.
__device__ void prep_item(int o, int i,
                          const float* __restrict__ raw_gamma,
                          const float* __restrict__ w,
                          const float* __restrict__ breaks,
                          const float* __restrict__ coefs,
                          const float* __restrict__ mu_p,
                          const float* __restrict__ sigma_p)
{
    float mu = mu_p[0];
    float sigma = sigma_p[0];

    float wv = w[o * IN_SZ + i];
    wv = fminf(fmaxf(wv, -5.5f), 37.9f);
    float wn = (wv - mu) / sigma;

    float b[NS];
#pragma unroll
    for (int s = 0; s < NS; s++) {
        const float* br = breaks + s * NB;
        float lo = br[0];
        float hi = br[NB - 1] - 1e-6f;
        float wl = fminf(fmaxf(wn, lo), hi);
        // searchsorted(br, wl, 'left') - 1  ==  (#elements < wl) - 1
        int idx = -1;
#pragma unroll
        for (int j = 0; j < NB; j++) idx += (br[j] < wl) ? 1 : 0;
        idx = max(0, min(idx, NI - 1));
        const float* cf = coefs + (s * NI + idx) * 4;
        float t = wl - br[idx];
        b[s] = ((cf[0] * t + cf[1]) * t + cf[2]) * t + cf[3];
    }

    float g = raw_gamma[o * IN_SZ + i];
    float sp = fmaxf(g, 0.0f) + log1pf(__expf(-fabsf(g)));   // stable softplus
    float scale = sp * (1.0f / OUT_SZ);

    g_PA[i * OUT_SZ + o] = make_float4(b[0] * scale * LN2f,  // b1'
                                       b[1] * LN2f,          // b2'
                                       b[2] * L2Ef,          // b3'
                                       b[3]);                // b4
    g_PB[i * OUT_SZ + o] = make_float4(b[4] * scale, b[5] * scale,
                                       b[6] * scale, b[7] * scale);
}

// One live evaluation: 5 MUFU + 10 fma-pipe ops.
__device__ __forceinline__ void eval1(float xv, float4 pa, float4 pb, float& acc)
{
    float e     = ex2f(pa.z * xv);           // exp(b3*x) == 2^(b3' x)
    float u     = e - 1.0f;
    float p     = ex2f(pa.w * lg2f(u));      // u^b4
    float L1    = lg2f(1.0f + p);            // log1p/ln2
    float inner = fmaf(pa.y, L1, 1.0f);      // 1 + b2*log1p
    float L2    = lg2f(inner);
    float h     = fmaf(pb.w, xv, pb.z);
    h           = fmaf(h, xv, pb.y);
    h           = fmaf(h, xv, pb.x);
    acc         = fmaf(xv, h, acc);
    acc         = fmaf(pa.x, L2, acc);       // + b1*scale*ln(inner)
}

// Fused kernel. block = (64, 4): 4 batch rows x 64 o's.
// Blocks 0..63 additionally compute one o-column of the prep table first.
__global__ __launch_bounds__(OUT_SZ * ROWS_PER_BLK)
void fused_kernel(const float* __restrict__ x, float* __restrict__ out,
                  const float* __restrict__ raw_gamma,
                  const float* __restrict__ w,
                  const float* __restrict__ breaks,
                  const float* __restrict__ coefs,
                  const float* __restrict__ mu_p,
                  const float* __restrict__ sigma_p)
{
    __shared__ float  rawx[ROWS_PER_BLK][IN_SZ];
    __shared__ float2 comp[ROWS_PER_BLK][IN_SZ];   // (x, float-bits of i*64)
    __shared__ int    cnt[ROWS_PER_BLK];

    const int o    = threadIdx.x;              // 0..63 (output index)
    const int ry   = threadIdx.y;              // 0..3  (row within block)
    const int tid  = o + (ry << 6);            // 0..255 linear
    const int bid  = blockIdx.x;
    const int row  = bid * ROWS_PER_BLK + ry;
    const int lane = o & 31;

    // ---- prep phase: blocks 0..63 each publish o-column = bid ----
    if (bid < PREP_BLOCKS) {
        if (tid < IN_SZ)
            prep_item(bid, tid, raw_gamma, w, breaks, coefs, mu_p, sigma_p);
        __syncthreads();
        if (tid == 0) {
            __threadfence();
            atomicAdd(&g_done, 1u);
        }
    }

    // ---- x load + per-row compaction (independent of the tables) ----
    rawx[ry][o] = fmaxf(x[row * IN_SZ + o], 0.0f);
    __syncthreads();

    if (o < 32) {                               // lower warp of each row
        float v0 = rawx[ry][lane];
        float v1 = rawx[ry][lane + 32];
        unsigned m0 = __ballot_sync(0xffffffffu, v0 > 0.0f);
        unsigned m1 = __ballot_sync(0xffffffffu, v1 > 0.0f);
        int n0 = __popc(m0);
        unsigned below = (1u << lane) - 1u;
        if (v0 > 0.0f)
            comp[ry][__popc(m0 & below)] =
                make_float2(v0, __int_as_float(lane << 6));
        if (v1 > 0.0f)
            comp[ry][n0 + __popc(m1 & below)] =
                make_float2(v1, __int_as_float((lane + 32) << 6));
        if (lane == 0) cnt[ry] = n0 + __popc(m1);
    }

    // ---- wait for all prep columns (one spinner per block) ----
    if (tid == 0) {
        while (ld_acquire(&g_done) < PREP_BLOCKS) __nanosleep(64);
    }
    __syncthreads();   // also publishes comp/cnt to the whole block

    // ---- mainloop: branchless over the compacted live list ----
    const int n = cnt[ry];
    float acc = 0.0f;

#pragma unroll 2
    for (int c = 0; c < n; c++) {
        float2 e = comp[ry][c];                 // broadcast LDS.64
        float xv = e.x;
        int ib   = __float_as_int(e.y);         // i*64
        float4 pa = g_PA[ib + o];
        float4 pb = g_PB[ib + o];
        eval1(xv, pa, pb, acc);
    }

    out[row * OUT_SZ + o] = acc;

    // ---- epilogue: last block resets the barrier for the next replay ----
    __syncthreads();
    if (tid == 0) {
        unsigned v = atomicAdd(&g_consumed, 1u);
        if (v == NBLK - 1u) {
            g_done = 0u;
            g_consumed = 0u;
        }
    }
}

extern "C" void kernel_launch(void* const* d_in, const int* in_sizes, int n_in,
                              void* d_out, int out_size)
{
    // metadata order: x, raw_gamma, w, breaks, coefs, mu_detuning, sigma_detuning
    const float* x         = (const float*)d_in[0];
    const float* raw_gamma = (const float*)d_in[1];
    const float* w         = (const float*)d_in[2];
    const float* breaks    = (const float*)d_in[3];
    const float* coefs     = (const float*)d_in[4];
    const float* mu        = (const float*)d_in[5];
    const float* sigma     = (const float*)d_in[6];
    float* out = (float*)d_out;

    dim3 blk(OUT_SZ, ROWS_PER_BLK);
    fused_kernel<<<NBLK, blk>>>(x, out, raw_gamma, w, breaks, coefs, mu, sigma);
}

// round 14
// speedup vs baseline: 1.3790x; 1.3790x over previous
#include <cuda_runtime.h>

#define B_SZ   8192
#define IN_SZ  64
#define OUT_SZ 64
#define NS     8
#define NB     20
#define NI     19

#define ROWS_PER_BLK 4
#define LN2f  0.69314718055994530942f
#define L2Ef  1.44269504088896340736f

// Precomputed per-(o,i) parameter tables, [i*OUT + o] layout (coalesced over o).
// PA = { b1*scale*ln2, b2*ln2, b3*log2e, b4 }
// PB = { b5..b8 * scale },  scale = softplus(raw_gamma)/OUT
__device__ float4 g_PA[IN_SZ * OUT_SZ];
__device__ float4 g_PB[IN_SZ * OUT_SZ];

__device__ __forceinline__ float ex2f(float x) {
    float y; asm("ex2.approx.ftz.f32 %0, %1;" : "=f"(y) : "f"(x)); return y;
}
__device__ __forceinline__ float lg2f(float x) {
    float y; asm("lg2.approx.ftz.f32 %0, %1;" : "=f"(y) : "f"(x)); return y;
}

// Thread per (o, i, s): 64*64*8 = 32768 threads, one spline eval each.
__global__ void prep_kernel(const float* __restrict__ raw_gamma,
                            const float* __restrict__ w,
                            const float* __restrict__ breaks,
                            const float* __restrict__ coefs,
                            const float* __restrict__ mu_p,
                            const float* __restrict__ sigma_p)
{
    int tid = blockIdx.x * blockDim.x + threadIdx.x;
    if (tid < IN_SZ * OUT_SZ * NS) {
        int s = tid & 7;
        int i = (tid >> 3) & 63;
        int o = tid >> 9;

        float mu = mu_p[0];
        float sigma = sigma_p[0];

        float wv = w[o * IN_SZ + i];
        wv = fminf(fmaxf(wv, -5.5f), 37.9f);
        float wn = (wv - mu) / sigma;

        const float* br = breaks + s * NB;
        float lo = br[0];
        float hi = br[NB - 1] - 1e-6f;
        float wl = fminf(fmaxf(wn, lo), hi);
        // searchsorted(br, wl, 'left') - 1  ==  (#elements < wl) - 1
        int idx = -1;
#pragma unroll
        for (int j = 0; j < NB; j++) idx += (br[j] < wl) ? 1 : 0;
        idx = max(0, min(idx, NI - 1));
        const float* cf = coefs + (s * NI + idx) * 4;
        float t = wl - br[idx];
        float b = ((cf[0] * t + cf[1]) * t + cf[2]) * t + cf[3];

        float g = raw_gamma[o * IN_SZ + i];
        float sp = fmaxf(g, 0.0f) + log1pf(__expf(-fabsf(g)));   // stable softplus
        float scale = sp * (1.0f / OUT_SZ);

        // s: 0 -> b1*scale*ln2 | 1 -> b2*ln2 | 2 -> b3*log2e | 3 -> b4
        //    4..7 -> b5..b8 * scale
        float mult;
        if      (s == 0) mult = scale * LN2f;
        else if (s == 1) mult = LN2f;
        else if (s == 2) mult = L2Ef;
        else if (s == 3) mult = 1.0f;
        else             mult = scale;

        float* dst = (s < 4) ? (float*)g_PA : (float*)g_PB;
        dst[(i * OUT_SZ + o) * 4 + (s & 3)] = b * mult;
    }
    // PDL flush: table writes are visible to the dependent grid after its wait.
    asm volatile("griddepcontrol.launch_dependents;");
}

// block = (64, 4): 4 batch rows x 64 o's; 2 warps per row.
// Phase 1: lower warp of each row loads x and ballot-compacts live i's
// (storing the table BYTE offset i<<10). Phase 2: branchless mainloop.
__global__ __launch_bounds__(OUT_SZ * ROWS_PER_BLK, 8)
void main_kernel(const float* __restrict__ x, float* __restrict__ out)
{
    __shared__ float2 comp[ROWS_PER_BLK][IN_SZ];   // (x, float-bits of i*1024)
    __shared__ int    cnt[ROWS_PER_BLK];

    const int o    = threadIdx.x;              // 0..63 (output index)
    const int ry   = threadIdx.y;              // 0..3  (row within block)
    const int row  = blockIdx.x * ROWS_PER_BLK + ry;
    const int lane = o & 31;

    if (o < 32) {                               // lower warp of each row
        float v0 = fmaxf(x[row * IN_SZ + lane], 0.0f);
        float v1 = fmaxf(x[row * IN_SZ + lane + 32], 0.0f);
        unsigned m0 = __ballot_sync(0xffffffffu, v0 > 0.0f);
        unsigned m1 = __ballot_sync(0xffffffffu, v1 > 0.0f);
        int n0 = __popc(m0);
        unsigned below = (1u << lane) - 1u;
        if (v0 > 0.0f)
            comp[ry][__popc(m0 & below)] =
                make_float2(v0, __int_as_float(lane << 10));
        if (v1 > 0.0f)
            comp[ry][n0 + __popc(m1 & below)] =
                make_float2(v1, __int_as_float((lane + 32) << 10));
        if (lane == 0) cnt[ry] = n0 + __popc(m1);
    }

    // Wait for prep's table writes (PDL dependency), then publish comp/cnt.
    asm volatile("griddepcontrol.wait;");
    __syncthreads();

    const int n = cnt[ry];
    const char* paBase = (const char*)(g_PA + o);   // + (i<<10) per entry
    const char* pbBase = (const char*)(g_PB + o);
    float accL = 0.0f, accP = 0.0f;

#pragma unroll 2
    for (int c = 0; c < n; c++) {
        float2 e = comp[ry][c];                 // broadcast LDS.64
        float xv = e.x;
        int ib   = __float_as_int(e.y);         // byte offset i*1024
        float4 pa = *(const float4*)(paBase + ib);
        float4 pb = *(const float4*)(pbBase + ib);

        float ex    = ex2f(pa.z * xv);          // exp(b3*x) == 2^(b3' x)
        float u     = ex - 1.0f;
        float p     = ex2f(pa.w * lg2f(u));     // u^b4
        float L1    = lg2f(1.0f + p);           // log1p/ln2
        float L2    = lg2f(fmaf(pa.y, L1, 1.0f));
        float h     = fmaf(pb.w, xv, pb.z);
        h           = fmaf(h, xv, pb.y);
        h           = fmaf(h, xv, pb.x);
        accP        = fmaf(xv, h, accP);        // polynomial part
        accL        = fmaf(pa.x, L2, accL);     // log part
    }

    out[row * OUT_SZ + o] = accL + accP;
}

extern "C" void kernel_launch(void* const* d_in, const int* in_sizes, int n_in,
                              void* d_out, int out_size)
{
    // metadata order: x, raw_gamma, w, breaks, coefs, mu_detuning, sigma_detuning
    const float* x         = (const float*)d_in[0];
    const float* raw_gamma = (const float*)d_in[1];
    const float* w         = (const float*)d_in[2];
    const float* breaks    = (const float*)d_in[3];
    const float* coefs     = (const float*)d_in[4];
    const float* mu        = (const float*)d_in[5];
    const float* sigma     = (const float*)d_in[6];
    float* out = (float*)d_out;

    prep_kernel<<<128, 256>>>(raw_gamma, w, breaks, coefs, mu, sigma);

    // PDL: main's launch ramp + x-load + compaction overlap prep's execution.
    cudaLaunchConfig_t cfg = {};
    cfg.gridDim  = dim3(B_SZ / ROWS_PER_BLK);
    cfg.blockDim = dim3(OUT_SZ, ROWS_PER_BLK);
    cfg.dynamicSmemBytes = 0;
    cudaLaunchAttribute attrs[1];
    attrs[0].id = cudaLaunchAttributeProgrammaticStreamSerialization;
    attrs[0].val.programmaticStreamSerializationAllowed = 1;
    cfg.attrs = attrs;
    cfg.numAttrs = 1;
    cudaLaunchKernelEx(&cfg, main_kernel, x, out);
}